// round 15
// baseline (speedup 1.0000x reference)
#include <cuda_runtime.h>
#include <cuda_bf16.h>
#include <cstdint>
#include <math.h>

#define NQ      32768
#define KC      8192
#define DD      256
#define MT      128           // queries per CTA
#define NTILE   128           // codes per tile
#define NTILES  (KC / NTILE)  // 64
#define NSTAGES (NTILES * 4)  // 256 (64-dim chunks)
#define WTH     1.0e-4f       // coarse trust window (>= 2x worst coarse error)
#define MAXC    8             // max stored candidates per query

// ---------------- device scratch (no cudaMalloc) ----------------------------
__device__ float         g_cbsq[KC];
__device__ __nv_bfloat16 g_cb_hi[KC * DD];
__device__ int           g_listA[NQ];
__device__ int           g_cntA;
__device__ int           g_listB[NQ];
__device__ int           g_cntB;
__device__ int           g_cands[NQ * MAXC];
__device__ int           g_ncand[NQ];

// ---------------- smem layout (bytes) ---------------------------------------
#define SM_A     0             // 64KB z tile; triage overlay later
#define SM_B     65536         // 3 stages x 16KB
#define SM_TOTAL 114688        // 112 KB

__device__ __forceinline__ uint32_t smem_u32(const void* p) {
    uint32_t a;
    asm("{ .reg .u64 t; cvta.to.shared.u64 t, %1; cvt.u32.u64 %0, t; }"
        : "=r"(a) : "l"(p));
    return a;
}
__device__ __forceinline__ uint32_t swz(uint32_t b) { return b ^ ((b >> 3) & 0x70); }

#define LDSM_X4(r0, r1, r2, r3, addr) \
    asm volatile("ldmatrix.sync.aligned.m8n8.x4.shared.b16 {%0,%1,%2,%3}, [%4];" \
                 : "=r"(r0), "=r"(r1), "=r"(r2), "=r"(r3) : "r"(addr))

#define MMA_BF16(c0, c1, c2, c3, a0, a1, a2, a3, b0, b1) \
    asm volatile("mma.sync.aligned.m16n8k16.row.col.f32.bf16.bf16.f32 " \
                 "{%0,%1,%2,%3}, {%4,%5,%6,%7}, {%8,%9}, {%0,%1,%2,%3};" \
                 : "+f"(c0), "+f"(c1), "+f"(c2), "+f"(c3) \
                 : "r"(a0), "r"(a1), "r"(a2), "r"(a3), "r"(b0), "r"(b1))

#define CP16(dst, src) \
    asm volatile("cp.async.cg.shared.global [%0], [%1], 16;" :: "r"(dst), "l"(src))
#define CP_COMMIT() asm volatile("cp.async.commit_group;" ::: "memory")
#define CP_WAIT(n)  asm volatile("cp.async.wait_group %0;" :: "n"(n) : "memory")

// ---------------------------------------------------------------------------
// Dummy no-op kernel: pads the launch index so ncu (-s 5 -c 1) profiles
// vq_mma_kernel instead of a tail kernel.
// ---------------------------------------------------------------------------
__global__ void dummy_kernel() {}

// ---------------------------------------------------------------------------
// Prep: codebook -> bf16 + ||e||^2; zero list counters. One warp per code.
// ---------------------------------------------------------------------------
__global__ void prep_kernel(const float* __restrict__ cb) {
    if (blockIdx.x == 0 && threadIdx.x == 0) { g_cntA = 0; g_cntB = 0; }
    int w = (blockIdx.x * blockDim.x + threadIdx.x) >> 5;
    int lane = threadIdx.x & 31;
    if (w >= KC) return;
    const float4* row = (const float4*)(cb + (size_t)w * DD);
    float s = 0.f;
    #pragma unroll
    for (int i = 0; i < 2; i++) {
        int f = lane + i * 32;
        float4 v = row[f];
        s += v.x * v.x + v.y * v.y + v.z * v.z + v.w * v.w;
        __nv_bfloat162 h0 = {__float2bfloat16_rn(v.x), __float2bfloat16_rn(v.y)};
        __nv_bfloat162 h1 = {__float2bfloat16_rn(v.z), __float2bfloat16_rn(v.w)};
        uint2 hu = {*(uint32_t*)&h0, *(uint32_t*)&h1};
        *(uint2*)(g_cb_hi + (size_t)w * DD + f * 4) = hu;
    }
    #pragma unroll
    for (int off = 16; off; off >>= 1) s += __shfl_xor_sync(0xffffffffu, s, off);
    if (lane == 0) g_cbsq[w] = s;
}

// ---------------------------------------------------------------------------
// Main: single-pass bf16 HMMA, deep-ILP inner loop (A frags preloaded,
// B frags double-buffered across k16), per-slot top-2 + window triage.
// 512 threads = 16 warps (4M x 4N). CTA: 128 queries x all 8192 codes.
// ---------------------------------------------------------------------------
__global__ void __launch_bounds__(512, 1)
vq_mma_kernel(const float* __restrict__ z, float* __restrict__ out) {
    extern __shared__ char smem[];
    const uint32_t sb = smem_u32(smem);
    const int tid  = threadIdx.x;
    const int wid  = tid >> 5;
    const int lane = tid & 31;
    const int wm   = wid >> 2;
    const int wn   = wid & 3;
    const int qbase = blockIdx.x * MT;

    const int cp_row0 = tid >> 3;
    const int cp_row1 = (tid + 512) >> 3;
    const int cp_c8   = (tid & 7) * 8;
    const uint32_t cp_o0 = swz((uint32_t)(cp_row0 * 128 + cp_c8 * 2));
    const uint32_t cp_o1 = swz((uint32_t)(cp_row1 * 128 + cp_c8 * 2));

    // prologue: issue B stages 0,1
    #pragma unroll
    for (int s = 0; s < 2; s++) {
        const uint32_t bst = sb + SM_B + s * 16384;
        const int tile = s >> 2, dc = s & 3;
        size_t src0 = (size_t)(tile * NTILE + cp_row0) * DD + dc * 64 + cp_c8;
        size_t src1 = (size_t)(tile * NTILE + cp_row1) * DD + dc * 64 + cp_c8;
        CP16(bst + cp_o0, g_cb_hi + src0);
        CP16(bst + cp_o1, g_cb_hi + src1);
        CP_COMMIT();
    }

    // convert z tile to swizzled bf16 chunks
    #pragma unroll
    for (int i = 0; i < 16; i++) {
        int id  = tid + i * 512;
        int row = id >> 6;
        int col = (id & 63) * 4;
        int dc  = col >> 6;
        int cl  = col & 63;
        float4 v = *(const float4*)(z + (size_t)(qbase + row) * DD + col);
        __nv_bfloat162 h0 = {__float2bfloat16_rn(v.x), __float2bfloat16_rn(v.y)};
        __nv_bfloat162 h1 = {__float2bfloat16_rn(v.z), __float2bfloat16_rn(v.w)};
        uint2 hu = {*(uint32_t*)&h0, *(uint32_t*)&h1};
        uint32_t o = (uint32_t)(dc * 16384) + swz((uint32_t)(row * 128 + cl * 2));
        *(uint2*)(smem + SM_A + o) = hu;
    }

    const int a_r  = wm * 32 + (lane & 15);
    const int a_c8 = (lane >> 4) * 8;
    const int b_r  = wn * 32 + (lane & 7) + ((lane >> 4) & 1) * 8;
    const int b_c8 = ((lane >> 3) & 1) * 8;

    float t1d[4], t2d[4];
    int   t1i[4];
    #pragma unroll
    for (int s = 0; s < 4; s++) { t1d[s] = INFINITY; t2d[s] = INFINITY; t1i[s] = 0x7fffffff; }

    float acc[2][4][4] = {};

    #pragma unroll 1
    for (int s = 0; s < NSTAGES; s++) {
        const int tile = s >> 2;
        const int dc   = s & 3;
        const uint32_t buf = sb + SM_B + (uint32_t)(s % 3) * 16384;

        if (s + 1 < NSTAGES) { CP_WAIT(1); } else { CP_WAIT(0); }
        __syncthreads();

        if (s + 2 < NSTAGES) {
            const int nt_ = (s + 2) >> 2, ndc = (s + 2) & 3;
            const uint32_t bst = sb + SM_B + (uint32_t)((s + 2) % 3) * 16384;
            size_t src0 = (size_t)(nt_ * NTILE + cp_row0) * DD + ndc * 64 + cp_c8;
            size_t src1 = (size_t)(nt_ * NTILE + cp_row1) * DD + ndc * 64 + cp_c8;
            CP16(bst + cp_o0, g_cb_hi + src0);
            CP16(bst + cp_o1, g_cb_hi + src1);
            CP_COMMIT();
        }

        const uint32_t a_base = sb + SM_A + dc * 16384;

        // ---- preload ALL A fragments for this stage (8 LDSM -> 32 regs) ----
        uint32_t ah[2][4][4];
        #pragma unroll
        for (int k16 = 0; k16 < 4; k16++)
            #pragma unroll
            for (int mt = 0; mt < 2; mt++) {
                uint32_t o = swz((uint32_t)((a_r + mt * 16) * 128 + (a_c8 + k16 * 16) * 2));
                LDSM_X4(ah[mt][k16][0], ah[mt][k16][1], ah[mt][k16][2], ah[mt][k16][3],
                        a_base + o);
            }

        // ---- B fragments double-buffered across k16 -------------------------
        uint32_t fh[2][2][4];   // [buf][np][4]
        #pragma unroll
        for (int np = 0; np < 2; np++) {
            uint32_t o = swz((uint32_t)((b_r + np * 16) * 128 + b_c8 * 2));
            LDSM_X4(fh[0][np][0], fh[0][np][1], fh[0][np][2], fh[0][np][3], buf + o);
        }

        #pragma unroll
        for (int k16 = 0; k16 < 4; k16++) {
            const int cur = k16 & 1, nxt = cur ^ 1;
            if (k16 < 3) {
                const int kc = (k16 + 1) * 16;
                #pragma unroll
                for (int np = 0; np < 2; np++) {
                    uint32_t o = swz((uint32_t)((b_r + np * 16) * 128 + (b_c8 + kc) * 2));
                    LDSM_X4(fh[nxt][np][0], fh[nxt][np][1], fh[nxt][np][2], fh[nxt][np][3],
                            buf + o);
                }
            }
            #pragma unroll
            for (int mt = 0; mt < 2; mt++)
                #pragma unroll
                for (int nt = 0; nt < 4; nt++) {
                    float* c = acc[mt][nt];
                    MMA_BF16(c[0], c[1], c[2], c[3],
                             ah[mt][k16][0], ah[mt][k16][1], ah[mt][k16][2], ah[mt][k16][3],
                             fh[cur][nt >> 1][(nt & 1) * 2],
                             fh[cur][nt >> 1][(nt & 1) * 2 + 1]);
                }
        }

        // ---- epilogue on tile boundary: per-thread top-2 per row-slot ------
        if (dc == 3) {
            const int nbase = tile * NTILE;
            #pragma unroll
            for (int mt = 0; mt < 2; mt++)
                #pragma unroll
                for (int half = 0; half < 2; half++) {
                    const int slot = mt * 2 + half;
                    #pragma unroll
                    for (int nt = 0; nt < 4; nt++) {
                        const int coll = wn * 32 + nt * 8 + (lane & 3) * 2;
                        #pragma unroll
                        for (int p = 0; p < 2; p++) {
                            float cq = __ldg(&g_cbsq[nbase + coll + p]);
                            float d  = cq - 2.0f * acc[mt][nt][half * 2 + p];
                            int gi = nbase + coll + p;
                            if (d < t1d[slot] || (d == t1d[slot] && gi < t1i[slot])) {
                                t2d[slot] = t1d[slot]; t1d[slot] = d; t1i[slot] = gi;
                            } else if (d < t2d[slot]) {
                                t2d[slot] = d;
                            }
                        }
                    }
                }
            #pragma unroll
            for (int mt = 0; mt < 2; mt++)
                #pragma unroll
                for (int nt = 0; nt < 4; nt++)
                    #pragma unroll
                    for (int p = 0; p < 4; p++)
                        acc[mt][nt][p] = 0.f;
        }
    }

    // ---- dump per-slot top-2 to smem (overlay on A) --------------------------
    __syncthreads();
    float* sd1 = (float*)(smem);            // [128][16]
    int*   si1 = (int*)(smem + 8192);       // [128][16]
    float* sd2 = (float*)(smem + 16384);    // [128][16]

    #pragma unroll
    for (int slot = 0; slot < 4; slot++) {
        int row  = wm * 32 + (slot >> 1) * 16 + (slot & 1) * 8 + (lane >> 2);
        int sidx = wn * 4 + (lane & 3);     // disjoint code subset per sidx
        sd1[row * 16 + sidx] = t1d[slot];
        si1[row * 16 + sidx] = t1i[slot];
        sd2[row * 16 + sidx] = t2d[slot];
    }
    __syncthreads();

    // ---- per-query triage ----------------------------------------------------
    if (tid < MT) {
        const int q = qbase + tid;
        float c1 = INFINITY; int c1i = 0x7fffffff;
        #pragma unroll
        for (int s2 = 0; s2 < 16; s2++) {
            float d = sd1[tid * 16 + s2];
            int   i = si1[tid * 16 + s2];
            if (d < c1 || (d == c1 && i < c1i)) { c1 = d; c1i = i; }
        }
        const float win = c1 + WTH;
        bool t2in = false;
        int  n = 0;
        int  cands[MAXC];
        #pragma unroll
        for (int s2 = 0; s2 < 16; s2++) {
            if (sd2[tid * 16 + s2] < win) t2in = true;
            float d = sd1[tid * 16 + s2];
            if (d < win) {
                if (n < MAXC) cands[n] = si1[tid * 16 + s2];
                n++;
            }
        }
        out[q] = (float)c1i;
        if (t2in || n > MAXC) {
            int pos = atomicAdd(&g_cntB, 1);
            g_listB[pos] = q;
        } else if (n > 1) {
            #pragma unroll
            for (int j = 0; j < MAXC; j++)
                if (j < n) g_cands[q * MAXC + j] = cands[j];
            g_ncand[q] = n;
            int pos = atomicAdd(&g_cntA, 1);
            g_listA[pos] = q;
        }
    }
}

// ---------------------------------------------------------------------------
// Recheck A: exact fp32 distance over stored candidates (warp per query).
// ---------------------------------------------------------------------------
__global__ void recheckA_kernel(const float* __restrict__ z,
                                const float* __restrict__ cb,
                                float* __restrict__ out) {
    const int gw    = (blockIdx.x * blockDim.x + threadIdx.x) >> 5;
    const int lane  = threadIdx.x & 31;
    const int nwarp = (gridDim.x * blockDim.x) >> 5;

    const int count = g_cntA;
    for (int it = gw; it < count; it += nwarp) {
        const int q = g_listA[it];
        const int n = g_ncand[q];

        float zr[8];
        #pragma unroll
        for (int i = 0; i < 8; i++) zr[i] = z[(size_t)q * DD + lane + i * 32];

        float bd = INFINITY;
        int   bi = 0x7fffffff;
        for (int j = 0; j < n; j++) {
            int idx = g_cands[q * MAXC + j];
            const float* cr = cb + (size_t)idx * DD;
            float dot = 0.f;
            #pragma unroll
            for (int i = 0; i < 8; i++) dot = fmaf(zr[i], cr[lane + i * 32], dot);
            #pragma unroll
            for (int off = 16; off; off >>= 1) dot += __shfl_xor_sync(0xffffffffu, dot, off);
            float dist = g_cbsq[idx] - 2.0f * dot;
            if (dist < bd || (dist == bd && idx < bi)) { bd = dist; bi = idx; }
        }
        if (lane == 0) out[q] = (float)bi;
    }
}

// ---------------------------------------------------------------------------
// Fallback B: exact fp32 full scan (rare). 256-thr block strides the list.
// ---------------------------------------------------------------------------
__global__ void fallbackB_kernel(const float* __restrict__ z,
                                 const float* __restrict__ cb,
                                 float* __restrict__ out) {
    const int tid  = threadIdx.x;
    const int wid  = tid >> 5;
    const int lane = tid & 31;
    __shared__ float swd[8];
    __shared__ int   swi[8];

    const int count = g_cntB;
    for (int it = blockIdx.x; it < count; it += gridDim.x) {
        const int q = g_listB[it];

        float zr[8];
        #pragma unroll
        for (int i = 0; i < 8; i++) zr[i] = z[(size_t)q * DD + lane + i * 32];

        float bd = INFINITY;
        int   bi = 0x7fffffff;
        const int n0 = wid * (KC / 8);
        #pragma unroll 2
        for (int k = 0; k < KC / 8; k++) {
            const int n = n0 + k;
            const float* cr = cb + (size_t)n * DD;
            float dot = 0.f;
            #pragma unroll
            for (int i = 0; i < 8; i++) dot = fmaf(zr[i], cr[lane + i * 32], dot);
            #pragma unroll
            for (int off = 16; off; off >>= 1) dot += __shfl_xor_sync(0xffffffffu, dot, off);
            float dist = g_cbsq[n] - 2.0f * dot;
            if (dist < bd) { bd = dist; bi = n; }
        }
        if (lane == 0) { swd[wid] = bd; swi[wid] = bi; }
        __syncthreads();
        if (tid == 0) {
            float d = swd[0]; int i1 = swi[0];
            #pragma unroll
            for (int w = 1; w < 8; w++) {
                if (swd[w] < d || (swd[w] == d && swi[w] < i1)) { d = swd[w]; i1 = swi[w]; }
            }
            out[q] = (float)i1;
        }
        __syncthreads();
    }
}

// ---------------------------------------------------------------------------
extern "C" void kernel_launch(void* const* d_in, const int* in_sizes, int n_in,
                              void* d_out, int out_size) {
    // z_e_x is always the larger buffer (4x codebook).
    const float* z;
    const float* cb;
    if (in_sizes[0] >= in_sizes[1]) { z = (const float*)d_in[0]; cb = (const float*)d_in[1]; }
    else                            { cb = (const float*)d_in[0]; z = (const float*)d_in[1]; }
    float* out = (float*)d_out;

    cudaFuncSetAttribute(vq_mma_kernel,
                         cudaFuncAttributeMaxDynamicSharedMemorySize, SM_TOTAL);

    prep_kernel<<<KC / 8, 256>>>(cb);          // launch 0
    dummy_kernel<<<1, 32>>>();                 // launch 1
    dummy_kernel<<<1, 32>>>();                 // launch 2
    dummy_kernel<<<1, 32>>>();                 // launch 3
    dummy_kernel<<<1, 32>>>();                 // launch 4
    vq_mma_kernel<<<NQ / MT, 512, SM_TOTAL>>>(z, out);   // launch 5 (ncu -s 5)
    recheckA_kernel<<<1024, 256>>>(z, cb, out);
    fallbackB_kernel<<<256, 256>>>(z, cb, out);
}

// round 16
// speedup vs baseline: 1.0697x; 1.0697x over previous
#include <cuda_runtime.h>
#include <cuda_bf16.h>
#include <cstdint>
#include <math.h>

#define NQ      32768
#define KC      8192
#define DD      256
#define MT      64            // queries per CTA
#define NTILE   128           // codes per tile
#define NTILES  (KC / NTILE)  // 64
#define NSTAGES (NTILES * 4)  // 256 (64-dim chunks)
#define WTH     1.0e-4f       // coarse trust window (>= 2x worst coarse error)
#define MAXC    8             // max stored candidates per query

// ---------------- device scratch (no cudaMalloc) ----------------------------
__device__ float         g_cbsq[KC];
__device__ __nv_bfloat16 g_cb_hi[KC * DD];
__device__ int           g_listA[NQ];
__device__ int           g_cntA;
__device__ int           g_listB[NQ];
__device__ int           g_cntB;
__device__ int           g_cands[NQ * MAXC];
__device__ int           g_ncand[NQ];

// ---------------- smem layout (bytes) ---------------------------------------
// A: 4 dc-chunks x (64 x 64 bf16 SW128, 8KB) = 32KB
// B: 3 stages x 16KB = 48KB ; triage overlays A after the mainloop (12KB)
#define SM_A     0
#define SM_B     32768
#define SM_TOTAL 83968         // 82 KB -> 2 CTAs/SM

__device__ __forceinline__ uint32_t smem_u32(const void* p) {
    uint32_t a;
    asm("{ .reg .u64 t; cvta.to.shared.u64 t, %1; cvt.u32.u64 %0, t; }"
        : "=r"(a) : "l"(p));
    return a;
}
__device__ __forceinline__ uint32_t swz(uint32_t b) { return b ^ ((b >> 3) & 0x70); }

#define LDSM_X4(r0, r1, r2, r3, addr) \
    asm volatile("ldmatrix.sync.aligned.m8n8.x4.shared.b16 {%0,%1,%2,%3}, [%4];" \
                 : "=r"(r0), "=r"(r1), "=r"(r2), "=r"(r3) : "r"(addr))

#define MMA_BF16(c0, c1, c2, c3, a0, a1, a2, a3, b0, b1) \
    asm volatile("mma.sync.aligned.m16n8k16.row.col.f32.bf16.bf16.f32 " \
                 "{%0,%1,%2,%3}, {%4,%5,%6,%7}, {%8,%9}, {%0,%1,%2,%3};" \
                 : "+f"(c0), "+f"(c1), "+f"(c2), "+f"(c3) \
                 : "r"(a0), "r"(a1), "r"(a2), "r"(a3), "r"(b0), "r"(b1))

#define CP16(dst, src) \
    asm volatile("cp.async.cg.shared.global [%0], [%1], 16;" :: "r"(dst), "l"(src))
#define CP_COMMIT() asm volatile("cp.async.commit_group;" ::: "memory")
#define CP_WAIT(n)  asm volatile("cp.async.wait_group %0;" :: "n"(n) : "memory")

// ---------------------------------------------------------------------------
// Prep: codebook -> bf16 + ||e||^2; zero list counters. One warp per code.
// ---------------------------------------------------------------------------
__global__ void prep_kernel(const float* __restrict__ cb) {
    if (blockIdx.x == 0 && threadIdx.x == 0) { g_cntA = 0; g_cntB = 0; }
    int w = (blockIdx.x * blockDim.x + threadIdx.x) >> 5;
    int lane = threadIdx.x & 31;
    if (w >= KC) return;
    const float4* row = (const float4*)(cb + (size_t)w * DD);
    float s = 0.f;
    #pragma unroll
    for (int i = 0; i < 2; i++) {
        int f = lane + i * 32;
        float4 v = row[f];
        s += v.x * v.x + v.y * v.y + v.z * v.z + v.w * v.w;
        __nv_bfloat162 h0 = {__float2bfloat16_rn(v.x), __float2bfloat16_rn(v.y)};
        __nv_bfloat162 h1 = {__float2bfloat16_rn(v.z), __float2bfloat16_rn(v.w)};
        uint2 hu = {*(uint32_t*)&h0, *(uint32_t*)&h1};
        *(uint2*)(g_cb_hi + (size_t)w * DD + f * 4) = hu;
    }
    #pragma unroll
    for (int off = 16; off; off >>= 1) s += __shfl_xor_sync(0xffffffffu, s, off);
    if (lane == 0) g_cbsq[w] = s;
}

// ---------------------------------------------------------------------------
// Main: single-pass bf16 HMMA, deep-ILP inner loop, per-slot top-2 + triage.
// 256 threads = 8 warps (2M x 4N), warp tile 32q x 32c. CTA: 64 q x 8192 c.
// 82KB smem -> 2 CTAs/SM; 512 threads/SM -> 128-reg budget (no spills).
// ---------------------------------------------------------------------------
__global__ void __launch_bounds__(256, 2)
vq_mma_kernel(const float* __restrict__ z, float* __restrict__ out) {
    extern __shared__ char smem[];
    const uint32_t sb = smem_u32(smem);
    const int tid  = threadIdx.x;
    const int wid  = tid >> 5;
    const int lane = tid & 31;
    const int wm   = wid >> 2;     // 0..1 -> 32 query rows each
    const int wn   = wid & 3;      // 0..3 -> 32 code cols each
    const int qbase = blockIdx.x * MT;

    // cp.async: 1024 chunks of 16B per 16KB stage, 4 per thread
    const int cp_c8 = (tid & 7) * 8;

    // prologue: issue B stages 0,1
    #pragma unroll
    for (int s = 0; s < 2; s++) {
        const uint32_t bst = sb + SM_B + s * 16384;
        const int tile = s >> 2, dc = s & 3;
        #pragma unroll
        for (int i = 0; i < 4; i++) {
            int id  = tid + i * 256;
            int row = id >> 3;
            uint32_t o = swz((uint32_t)(row * 128 + cp_c8 * 2));
            size_t src = (size_t)(tile * NTILE + row) * DD + dc * 64 + cp_c8;
            CP16(bst + o, g_cb_hi + src);
        }
        CP_COMMIT();
    }

    // convert z tile (64x256 fp32) to swizzled bf16 chunks (16 float4/thread)
    #pragma unroll
    for (int i = 0; i < 16; i++) {
        int id  = tid + i * 256;           // float4 id, 4096 total
        int row = id >> 6;                 // 0..63
        int col = (id & 63) * 4;
        int dc  = col >> 6;
        int cl  = col & 63;
        float4 v = *(const float4*)(z + (size_t)(qbase + row) * DD + col);
        __nv_bfloat162 h0 = {__float2bfloat16_rn(v.x), __float2bfloat16_rn(v.y)};
        __nv_bfloat162 h1 = {__float2bfloat16_rn(v.z), __float2bfloat16_rn(v.w)};
        uint2 hu = {*(uint32_t*)&h0, *(uint32_t*)&h1};
        uint32_t o = (uint32_t)(dc * 8192) + swz((uint32_t)(row * 128 + cl * 2));
        *(uint2*)(smem + SM_A + o) = hu;
    }

    const int a_r  = wm * 32 + (lane & 15);
    const int a_c8 = (lane >> 4) * 8;
    const int b_r  = wn * 32 + (lane & 7) + ((lane >> 4) & 1) * 8;
    const int b_c8 = ((lane >> 3) & 1) * 8;

    float t1d[4], t2d[4];
    int   t1i[4];
    #pragma unroll
    for (int s = 0; s < 4; s++) { t1d[s] = INFINITY; t2d[s] = INFINITY; t1i[s] = 0x7fffffff; }

    float acc[2][4][4] = {};

    #pragma unroll 1
    for (int s = 0; s < NSTAGES; s++) {
        const int tile = s >> 2;
        const int dc   = s & 3;
        const uint32_t buf = sb + SM_B + (uint32_t)(s % 3) * 16384;

        if (s + 1 < NSTAGES) { CP_WAIT(1); } else { CP_WAIT(0); }
        __syncthreads();

        if (s + 2 < NSTAGES) {
            const int nt_ = (s + 2) >> 2, ndc = (s + 2) & 3;
            const uint32_t bst = sb + SM_B + (uint32_t)((s + 2) % 3) * 16384;
            #pragma unroll
            for (int i = 0; i < 4; i++) {
                int id  = tid + i * 256;
                int row = id >> 3;
                uint32_t o = swz((uint32_t)(row * 128 + cp_c8 * 2));
                size_t src = (size_t)(nt_ * NTILE + row) * DD + ndc * 64 + cp_c8;
                CP16(bst + o, g_cb_hi + src);
            }
            CP_COMMIT();
        }

        const uint32_t a_base = sb + SM_A + dc * 8192;

        // ---- preload ALL A fragments for this stage (8 LDSM -> 32 regs) ----
        uint32_t ah[2][4][4];
        #pragma unroll
        for (int k16 = 0; k16 < 4; k16++)
            #pragma unroll
            for (int mt = 0; mt < 2; mt++) {
                uint32_t o = swz((uint32_t)((a_r + mt * 16) * 128 + (a_c8 + k16 * 16) * 2));
                LDSM_X4(ah[mt][k16][0], ah[mt][k16][1], ah[mt][k16][2], ah[mt][k16][3],
                        a_base + o);
            }

        // ---- B fragments double-buffered across k16 -------------------------
        uint32_t fh[2][2][4];   // [buf][np][4]
        #pragma unroll
        for (int np = 0; np < 2; np++) {
            uint32_t o = swz((uint32_t)((b_r + np * 16) * 128 + b_c8 * 2));
            LDSM_X4(fh[0][np][0], fh[0][np][1], fh[0][np][2], fh[0][np][3], buf + o);
        }

        #pragma unroll
        for (int k16 = 0; k16 < 4; k16++) {
            const int cur = k16 & 1, nxt = cur ^ 1;
            if (k16 < 3) {
                const int kc = (k16 + 1) * 16;
                #pragma unroll
                for (int np = 0; np < 2; np++) {
                    uint32_t o = swz((uint32_t)((b_r + np * 16) * 128 + (b_c8 + kc) * 2));
                    LDSM_X4(fh[nxt][np][0], fh[nxt][np][1], fh[nxt][np][2], fh[nxt][np][3],
                            buf + o);
                }
            }
            #pragma unroll
            for (int mt = 0; mt < 2; mt++)
                #pragma unroll
                for (int nt = 0; nt < 4; nt++) {
                    float* c = acc[mt][nt];
                    MMA_BF16(c[0], c[1], c[2], c[3],
                             ah[mt][k16][0], ah[mt][k16][1], ah[mt][k16][2], ah[mt][k16][3],
                             fh[cur][nt >> 1][(nt & 1) * 2],
                             fh[cur][nt >> 1][(nt & 1) * 2 + 1]);
                }
        }

        // ---- epilogue on tile boundary: per-thread top-2 per row-slot ------
        if (dc == 3) {
            const int nbase = tile * NTILE;
            #pragma unroll
            for (int mt = 0; mt < 2; mt++)
                #pragma unroll
                for (int half = 0; half < 2; half++) {
                    const int slot = mt * 2 + half;
                    #pragma unroll
                    for (int nt = 0; nt < 4; nt++) {
                        const int coll = wn * 32 + nt * 8 + (lane & 3) * 2;
                        #pragma unroll
                        for (int p = 0; p < 2; p++) {
                            float cq = __ldg(&g_cbsq[nbase + coll + p]);
                            float d  = cq - 2.0f * acc[mt][nt][half * 2 + p];
                            int gi = nbase + coll + p;
                            if (d < t1d[slot] || (d == t1d[slot] && gi < t1i[slot])) {
                                t2d[slot] = t1d[slot]; t1d[slot] = d; t1i[slot] = gi;
                            } else if (d < t2d[slot]) {
                                t2d[slot] = d;
                            }
                        }
                    }
                }
            #pragma unroll
            for (int mt = 0; mt < 2; mt++)
                #pragma unroll
                for (int nt = 0; nt < 4; nt++)
                    #pragma unroll
                    for (int p = 0; p < 4; p++)
                        acc[mt][nt][p] = 0.f;
        }
    }

    // ---- dump per-slot top-2 to smem (overlay on A) --------------------------
    __syncthreads();
    float* sd1 = (float*)(smem);            // [64][16]
    int*   si1 = (int*)(smem + 4096);       // [64][16]
    float* sd2 = (float*)(smem + 8192);     // [64][16]

    #pragma unroll
    for (int mt = 0; mt < 2; mt++)
        #pragma unroll
        for (int half = 0; half < 2; half++) {
            int slot = mt * 2 + half;
            int row  = wm * 32 + mt * 16 + half * 8 + (lane >> 2);
            int sidx = wn * 4 + (lane & 3);  // disjoint code subset per sidx
            sd1[row * 16 + sidx] = t1d[slot];
            si1[row * 16 + sidx] = t1i[slot];
            sd2[row * 16 + sidx] = t2d[slot];
        }
    __syncthreads();

    // ---- per-query triage ----------------------------------------------------
    if (tid < MT) {
        const int q = qbase + tid;
        float c1 = INFINITY; int c1i = 0x7fffffff;
        #pragma unroll
        for (int s2 = 0; s2 < 16; s2++) {
            float d = sd1[tid * 16 + s2];
            int   i = si1[tid * 16 + s2];
            if (d < c1 || (d == c1 && i < c1i)) { c1 = d; c1i = i; }
        }
        const float win = c1 + WTH;
        bool t2in = false;
        int  n = 0;
        int  cands[MAXC];
        #pragma unroll
        for (int s2 = 0; s2 < 16; s2++) {
            if (sd2[tid * 16 + s2] < win) t2in = true;
            float d = sd1[tid * 16 + s2];
            if (d < win) {
                if (n < MAXC) cands[n] = si1[tid * 16 + s2];
                n++;
            }
        }
        out[q] = (float)c1i;
        if (t2in || n > MAXC) {
            int pos = atomicAdd(&g_cntB, 1);
            g_listB[pos] = q;
        } else if (n > 1) {
            #pragma unroll
            for (int j = 0; j < MAXC; j++)
                if (j < n) g_cands[q * MAXC + j] = cands[j];
            g_ncand[q] = n;
            int pos = atomicAdd(&g_cntA, 1);
            g_listA[pos] = q;
        }
    }
}

// ---------------------------------------------------------------------------
// Recheck A: exact fp32 distance over stored candidates (warp per query).
// ---------------------------------------------------------------------------
__global__ void recheckA_kernel(const float* __restrict__ z,
                                const float* __restrict__ cb,
                                float* __restrict__ out) {
    const int gw    = (blockIdx.x * blockDim.x + threadIdx.x) >> 5;
    const int lane  = threadIdx.x & 31;
    const int nwarp = (gridDim.x * blockDim.x) >> 5;

    const int count = g_cntA;
    for (int it = gw; it < count; it += nwarp) {
        const int q = g_listA[it];
        const int n = g_ncand[q];

        float zr[8];
        #pragma unroll
        for (int i = 0; i < 8; i++) zr[i] = z[(size_t)q * DD + lane + i * 32];

        float bd = INFINITY;
        int   bi = 0x7fffffff;
        for (int j = 0; j < n; j++) {
            int idx = g_cands[q * MAXC + j];
            const float* cr = cb + (size_t)idx * DD;
            float dot = 0.f;
            #pragma unroll
            for (int i = 0; i < 8; i++) dot = fmaf(zr[i], cr[lane + i * 32], dot);
            #pragma unroll
            for (int off = 16; off; off >>= 1) dot += __shfl_xor_sync(0xffffffffu, dot, off);
            float dist = g_cbsq[idx] - 2.0f * dot;
            if (dist < bd || (dist == bd && idx < bi)) { bd = dist; bi = idx; }
        }
        if (lane == 0) out[q] = (float)bi;
    }
}

// ---------------------------------------------------------------------------
// Fallback B: exact fp32 full scan (rare). 256-thr block strides the list.
// ---------------------------------------------------------------------------
__global__ void fallbackB_kernel(const float* __restrict__ z,
                                 const float* __restrict__ cb,
                                 float* __restrict__ out) {
    const int tid  = threadIdx.x;
    const int wid  = tid >> 5;
    const int lane = tid & 31;
    __shared__ float swd[8];
    __shared__ int   swi[8];

    const int count = g_cntB;
    for (int it = blockIdx.x; it < count; it += gridDim.x) {
        const int q = g_listB[it];

        float zr[8];
        #pragma unroll
        for (int i = 0; i < 8; i++) zr[i] = z[(size_t)q * DD + lane + i * 32];

        float bd = INFINITY;
        int   bi = 0x7fffffff;
        const int n0 = wid * (KC / 8);
        #pragma unroll 2
        for (int k = 0; k < KC / 8; k++) {
            const int n = n0 + k;
            const float* cr = cb + (size_t)n * DD;
            float dot = 0.f;
            #pragma unroll
            for (int i = 0; i < 8; i++) dot = fmaf(zr[i], cr[lane + i * 32], dot);
            #pragma unroll
            for (int off = 16; off; off >>= 1) dot += __shfl_xor_sync(0xffffffffu, dot, off);
            float dist = g_cbsq[n] - 2.0f * dot;
            if (dist < bd) { bd = dist; bi = n; }
        }
        if (lane == 0) { swd[wid] = bd; swi[wid] = bi; }
        __syncthreads();
        if (tid == 0) {
            float d = swd[0]; int i1 = swi[0];
            #pragma unroll
            for (int w = 1; w < 8; w++) {
                if (swd[w] < d || (swd[w] == d && swi[w] < i1)) { d = swd[w]; i1 = swi[w]; }
            }
            out[q] = (float)i1;
        }
        __syncthreads();
    }
}

// ---------------------------------------------------------------------------
extern "C" void kernel_launch(void* const* d_in, const int* in_sizes, int n_in,
                              void* d_out, int out_size) {
    // z_e_x is always the larger buffer (4x codebook).
    const float* z;
    const float* cb;
    if (in_sizes[0] >= in_sizes[1]) { z = (const float*)d_in[0]; cb = (const float*)d_in[1]; }
    else                            { cb = (const float*)d_in[0]; z = (const float*)d_in[1]; }
    float* out = (float*)d_out;

    cudaFuncSetAttribute(vq_mma_kernel,
                         cudaFuncAttributeMaxDynamicSharedMemorySize, SM_TOTAL);

    prep_kernel<<<KC / 8, 256>>>(cb);
    vq_mma_kernel<<<NQ / MT, 256, SM_TOTAL>>>(z, out);
    recheckA_kernel<<<1024, 256>>>(z, cb, out);
    fallbackB_kernel<<<256, 256>>>(z, cb, out);
}